// round 17
// baseline (speedup 1.0000x reference)
#include <cuda_runtime.h>
#include <math.h>
#include <stdint.h>

// Problem shape (fixed by the dataset)
#define NROWS   32768      // B*T
#define DDIM    1024
#define KD      6
#define NP      8
#define THREADS 256
#define WARPS_PER_BLOCK 8
#define ROWS_PER_WARP 2
#define ROWS_PER_CTA 16                       // 8 warps x 2 rows
#define GRID    (NROWS / ROWS_PER_CTA)        // 2048
#define XBLK_FLOATS (ROWS_PER_CTA * DDIM)     // 16384 floats = 64 KB
#define XBLK_BYTES  (XBLK_FLOATS * 4)
#define BULK_PIECES 4
#define PIECE_BYTES (XBLK_BYTES / BULK_PIECES) // 16 KB

// dynamic smem layout (float index): W | xblock | protos | h | mbarrier
#define SM_W   0
#define SM_XB  (KD * DDIM)                    // 6144
#define SM_PS  (SM_XB + XBLK_FLOATS)          // 22528
#define SM_H   (SM_PS + NP * 8)               // 22592
#define SM_MB  (SM_H + 2)                     // 22594 -> byte 90376 (8B aligned)
#define SMEM_FLOATS (SM_MB + 2)               // 22596
#define SMEM_BYTES  (SMEM_FLOATS * 4)         // 90384 B -> 2 CTAs/SM

typedef unsigned long long u64;

// Packed dual-FMA (sm_103a FFMA2)
__device__ __forceinline__ void ffma2(u64& acc, u64 a, u64 b) {
    asm("fma.rn.f32x2 %0, %1, %2, %0;" : "+l"(acc) : "l"(a), "l"(b));
}
__device__ __forceinline__ float f32x2_sum(u64 v) {
    uint32_t lo, hi;
    asm("mov.b64 {%0, %1}, %2;" : "=r"(lo), "=r"(hi) : "l"(v));
    return __uint_as_float(lo) + __uint_as_float(hi);
}

// ---- mbarrier + 1D bulk-TMA primitives ----
__device__ __forceinline__ void mbar_init(uint32_t a, uint32_t cnt) {
    asm volatile("mbarrier.init.shared.b64 [%0], %1;" :: "r"(a), "r"(cnt) : "memory");
}
__device__ __forceinline__ void mbar_expect_tx(uint32_t a, uint32_t bytes) {
    asm volatile("mbarrier.arrive.expect_tx.shared.b64 _, [%0], %1;"
                 :: "r"(a), "r"(bytes) : "memory");
}
__device__ __forceinline__ void mbar_wait0(uint32_t a) {
    asm volatile(
        "{\n\t"
        ".reg .pred P;\n\t"
        "WL%=:\n\t"
        "mbarrier.try_wait.parity.acquire.cta.shared::cta.b64 P, [%0], 0, 0x989680;\n\t"
        "@P bra WD%=;\n\t"
        "bra WL%=;\n\t"
        "WD%=:\n\t"
        "}"
        :: "r"(a) : "memory");
}
// 1D bulk copy gmem -> smem (UBLKCP), completion via mbarrier complete_tx
__device__ __forceinline__ void bulk_ldg(uint32_t dst_smem, const void* gsrc,
                                         uint32_t bytes, uint32_t mbar) {
    asm volatile(
        "cp.async.bulk.shared::cta.global.mbarrier::complete_tx::bytes [%0], [%1], %2, [%3];"
        :: "r"(dst_smem), "l"(gsrc), "r"(bytes), "r"(mbar) : "memory");
}

__global__ __launch_bounds__(THREADS, 2)
void q6_kernel(const float* __restrict__ x,
               const float* __restrict__ W,
               const float* __restrict__ protos,
               const float* __restrict__ hs,
               float* __restrict__ out)
{
    extern __shared__ float smem[];
    float* w_s = smem + SM_W;
    float* p_s = smem + SM_PS;

    const int tid  = threadIdx.x;
    const int warp = tid >> 5;
    const int lane = tid & 31;
    const int cta_row0 = blockIdx.x * ROWS_PER_CTA;

    const uint32_t smem_base = (uint32_t)__cvta_generic_to_shared(smem);
    const uint32_t mbar      = smem_base + SM_MB * 4;
    const uint32_t xb_sa     = smem_base + SM_XB * 4;

    // ---- phase 1: barrier init (must happen-before ANY thread's wait)
    if (tid == 0) {
        mbar_init(mbar, 1);
        asm volatile("fence.proxy.async.shared::cta;" ::: "memory");
    }
    __syncthreads();

    // ---- phase 2: launch the 64KB x-block load (single expect_tx, 4 bulks)
    if (tid == 0) {
        mbar_expect_tx(mbar, XBLK_BYTES);
        #pragma unroll
        for (int pcs = 0; pcs < BULK_PIECES; ++pcs)
            bulk_ldg(xb_sa + (uint32_t)pcs * PIECE_BYTES,
                     x + (size_t)cta_row0 * DDIM + pcs * (PIECE_BYTES / 4),
                     PIECE_BYTES, mbar);
    }

    // ---- stage W into shared (overlaps with the TMA load)
    {
        const float4* Wv  = reinterpret_cast<const float4*>(W);
        float4*       wsv = reinterpret_cast<float4*>(w_s);
        #pragma unroll
        for (int i = 0; i < (KD * DDIM / 4) / THREADS; ++i)
            wsv[tid + i * THREADS] = Wv[tid + i * THREADS];
    }
    // ---- normalize prototypes into shared
    if (tid < NP) {
        float pv[KD]; float ss = 0.f;
        #pragma unroll
        for (int k = 0; k < KD; ++k) { pv[k] = protos[tid * KD + k]; ss += pv[k] * pv[k]; }
        float inv = 1.f / fmaxf(sqrtf(ss), 1e-12f);
        #pragma unroll
        for (int k = 0; k < KD; ++k) p_s[tid * 8 + k] = pv[k] * inv;
    }
    if (tid == 0) smem[SM_H] = hs[0];
    __syncthreads();          // W + p_s + h visible

    mbar_wait0(mbar);         // x-block landed (acquire orders the LDS reads below)

    // ---- GEMV: 2 rows per warp, 12 packed f32x2 accumulators
    u64 s2[ROWS_PER_WARP][KD];
    #pragma unroll
    for (int r = 0; r < ROWS_PER_WARP; ++r)
        #pragma unroll
        for (int k = 0; k < KD; ++k) s2[r][k] = 0ULL;

    const ulonglong2* xs  = reinterpret_cast<const ulonglong2*>(
                                smem + SM_XB + warp * ROWS_PER_WARP * DDIM);
    const ulonglong2* wv2 = reinterpret_cast<const ulonglong2*>(w_s);

    #pragma unroll
    for (int c = 0; c < DDIM / 128; ++c) {
        const int dq = c * 32 + lane;
        const ulonglong2 a0 = xs[0 * (DDIM / 4) + dq];
        const ulonglong2 a1 = xs[1 * (DDIM / 4) + dq];
        #pragma unroll
        for (int k = 0; k < KD; ++k) {
            const ulonglong2 w2 = wv2[k * (DDIM / 4) + dq];
            ffma2(s2[0][k], a0.x, w2.x); ffma2(s2[0][k], a0.y, w2.y);
            ffma2(s2[1][k], a1.x, w2.x); ffma2(s2[1][k], a1.y, w2.y);
        }
    }

    // ---- collapse packed pairs, then warp butterfly reduce
    float s[ROWS_PER_WARP][KD];
    #pragma unroll
    for (int r = 0; r < ROWS_PER_WARP; ++r)
        #pragma unroll
        for (int k = 0; k < KD; ++k) s[r][k] = f32x2_sum(s2[r][k]);

    #pragma unroll
    for (int off = 16; off > 0; off >>= 1)
        #pragma unroll
        for (int r = 0; r < ROWS_PER_WARP; ++r)
            #pragma unroll
            for (int k = 0; k < KD; ++k)
                s[r][k] += __shfl_xor_sync(0xffffffffu, s[r][k], off);

    // ---- epilogue: lanes 0..1 each finalize one row
    if (lane < ROWS_PER_WARP) {
        float zs[KD];
        #pragma unroll
        for (int k = 0; k < KD; ++k)
            zs[k] = (lane == 1) ? s[1][k] : s[0][k];

        float ss = 0.f;
        #pragma unroll
        for (int k = 0; k < KD; ++k) { zs[k] = tanhf(zs[k]); ss += zs[k] * zs[k]; }
        const float invn = 1.f / fmaxf(sqrtf(ss), 1e-6f);

        // softmax of -h*(3 - 3*dot) == softmax of (3*h*invn)*dot
        const float scale = 3.f * smem[SM_H] * invn;
        float lg[NP]; float mx = -1e30f;
        #pragma unroll
        for (int p = 0; p < NP; ++p) {
            float d = 0.f;
            #pragma unroll
            for (int k = 0; k < KD; ++k) d = fmaf(zs[k], p_s[p * 8 + k], d);
            lg[p] = scale * d;
            mx = fmaxf(mx, lg[p]);
        }
        float se = 0.f;
        #pragma unroll
        for (int p = 0; p < NP; ++p) { lg[p] = __expf(lg[p] - mx); se += lg[p]; }
        const float is = 1.f / se;

        const int row = cta_row0 + warp * ROWS_PER_WARP + lane;
        float4* o = reinterpret_cast<float4*>(out + (size_t)row * NP);
        o[0] = make_float4(lg[0] * is, lg[1] * is, lg[2] * is, lg[3] * is);
        o[1] = make_float4(lg[4] * is, lg[5] * is, lg[6] * is, lg[7] * is);
    }
}

extern "C" void kernel_launch(void* const* d_in, const int* in_sizes, int n_in,
                              void* d_out, int out_size)
{
    const float* x      = (const float*)d_in[0];   // (4,8192,1024) f32
    const float* W      = (const float*)d_in[1];   // (6,1024) f32
    const float* protos = (const float*)d_in[2];   // (8,6) f32
    const float* hs     = (const float*)d_in[3];   // scalar f32
    float*       out    = (float*)d_out;           // (4,8192,8) f32

    // opt in to >48KB dynamic smem (attribute set, not an allocation; idempotent)
    cudaFuncSetAttribute(q6_kernel, cudaFuncAttributeMaxDynamicSharedMemorySize, SMEM_BYTES);

    q6_kernel<<<GRID, THREADS, SMEM_BYTES>>>(x, W, protos, hs, out);
}